// round 8
// baseline (speedup 1.0000x reference)
#include <cuda_runtime.h>

// ---------------------------------------------------------------------------
// PETP_Quadratic v2: 4-element-per-warp register/LDS.128 blocked CTP.
//   y_s[w]   = sum_p WS[p,w] * PG[p]       (PG = 528 s-pairs + 528 gram pairs)
//   y_v[w,k] = sum_v (sum_u s_u WV[u,v,w]) v[v,k]
// ---------------------------------------------------------------------------

#define EDIM  98304
#define NPAIR 528
#define WS_FLOATS (1056*32)       // 33792, layout [p/4][w][4]
#define WV_FLOATS (32*32*36)      // 36864, layout [u][w][v pad 36]
#define NCTA   148
#define EPC    665                // 148*665 = 98420 >= 98304
#define NWARPS 16
#define CH     88                 // pairs per build chunk, 528 = 6*88
#define NCHUNK 6

__device__ float g_WS[4 * WS_FLOATS];
__device__ float g_WV[4 * WV_FLOATS];
__device__ unsigned short g_LUT[NPAIR];
__device__ float g_Xk[(size_t)EDIM * 4 * 128];

// ---------------------------------------------------------------------------
// Prep: blocks [0,1024) do weights, blocks [1024, 17408) do features.
// ---------------------------------------------------------------------------
__global__ void prep(const float* __restrict__ x,
                     const float* __restrict__ Ws, const float* __restrict__ Wf,
                     const float* __restrict__ Wn, const float* __restrict__ Wa) {
    int blk = blockIdx.x;
    if (blk < 1024) {
        int tid = blk * 128 + threadIdx.x;        // 0..131071
        int w = tid & 31;
        int v = (tid >> 5) & 31;
        int u = (tid >> 10) & 31;
        int t = tid >> 15;
        const float* Wt = (t == 0) ? Ws : (t == 1) ? Wf : (t == 2) ? Wn : Wa;
        const float norm = 0.022097086912079608f;   // 1/(32*sqrt(2))
        const float i3   = 0.5773502691896258f;     // 1/sqrt(3)

        float w2 = Wt[2*32768 + (u*32 + v)*32 + w];
        float w3 = Wt[3*32768 + (v*32 + u)*32 + w];
        g_WV[t*WV_FLOATS + u*1152 + w*36 + v] = norm * (w2 + w3);

        if (u <= v) {
            int p = ((u * (65 - u)) >> 1) + (v - u);
            float a0 = Wt[0*32768 + (u*32 + v)*32 + w];
            float a1 = Wt[1*32768 + (u*32 + v)*32 + w];
            if (u != v) {
                a0 += Wt[0*32768 + (v*32 + u)*32 + w];
                a1 += Wt[1*32768 + (v*32 + u)*32 + w];
            }
            int q  = p;
            int q2 = 528 + p;
            g_WS[t*WS_FLOATS + (q  >> 2)*128 + w*4 + (q  & 3)] = norm * a0;
            g_WS[t*WS_FLOATS + (q2 >> 2)*128 + w*4 + (q2 & 3)] = norm * i3 * a1;
            if (t == 0 && w == 0) g_LUT[p] = (unsigned short)(u | (v << 8));
        }
    } else {
        int b  = blk - 1024;     // 0..16383
        int ch = threadIdx.x;    // 0..127
        const float* xb = x + (size_t)b * 6 * 128 + ch;
        float xv[6];
        #pragma unroll
        for (int q = 0; q < 6; q++) xv[q] = xb[q * 128];
        float r0 = xv[0] + xv[1] + xv[2];
        float r1 = xv[3] + xv[4] + xv[5];
        float c0 = xv[0] + xv[3];
        float c1 = xv[1] + xv[4];
        float c2 = xv[2] + xv[5];
        float tot = r0 + r1;
        float* o = g_Xk + (size_t)b * 6 * 4 * 128 + ch;
        #pragma unroll
        for (int i = 0; i < 2; i++) {
            float ri = i ? r1 : r0;
            #pragma unroll
            for (int j = 0; j < 3; j++) {
                float cj = (j == 0) ? c0 : (j == 1) ? c1 : c2;
                float xs = xv[i*3 + j];
                float xf = (ri - xs) * 0.5f;
                float xn = (cj - xs);
                float xa = (tot - ri - cj + xs) * 0.5f;
                float* oe = o + (size_t)(i*3 + j) * 512;
                oe[0]   = xs;
                oe[128] = xf;
                oe[256] = xn;
                oe[384] = xa;
            }
        }
    }
}

// ---------------------------------------------------------------------------
// Main: 148 CTAs x 512 threads. Warp processes 4 elements at a time.
// ---------------------------------------------------------------------------
__global__ void __launch_bounds__(512, 1) petp_main(float* __restrict__ out) {
    extern __shared__ float sm[];
    float* Wsm     = sm;                                   // 36864 floats max
    float* PGall   = sm + WV_FLOATS;                       // 16 * 4 * 88
    float* featall = PGall + NWARPS * 4 * CH;              // 16 * 512
    float* S4all   = featall + NWARPS * 512;               // 16 * 128
    unsigned short* LUTs = (unsigned short*)(S4all + NWARPS * 128);  // 528 u16

    const int tid  = threadIdx.x;
    const int warp = tid >> 5;
    const int lane = tid & 31;
    float* PG   = PGall   + warp * 4 * CH;
    float* feat = featall + warp * 512;
    float* S4   = S4all   + warp * 128;

    for (int i = tid; i < NPAIR; i += 512) LUTs[i] = g_LUT[i];

    const int base  = blockIdx.x * EPC;
    const int count = (EPC < EDIM - base) ? EPC : (EDIM - base);

    for (int t = 0; t < 4; ++t) {
        // ================= scalar phase =================
        __syncthreads();
        {
            const float4* src = (const float4*)(g_WS + t * WS_FLOATS);
            float4* dst = (float4*)Wsm;
            for (int i = tid; i < WS_FLOATS/4; i += 512) dst[i] = src[i];
        }
        __syncthreads();

        for (int g = warp; g * 4 < count; g += NWARPS) {
            const int e0 = base + g * 4;
            #pragma unroll
            for (int e = 0; e < 4; ++e) {
                int ee = e0 + e; if (ee >= EDIM) ee = EDIM - 1;
                ((float4*)(feat + e*128))[lane] =
                    ((const float4*)(g_Xk + ((size_t)ee*4 + t)*128))[lane];
            }
            __syncwarp();

            float a0_0=0.f,a0_1=0.f,a0_2=0.f,a0_3=0.f;
            float a1_0=0.f,a1_1=0.f,a1_2=0.f,a1_3=0.f;

            #pragma unroll 1
            for (int h = 0; h < 2; ++h) {
                #pragma unroll 1
                for (int c = 0; c < NCHUNK; ++c) {
                    const int p0 = c * CH;
                    // ---- build chunk ----
                    for (int i = lane; i < CH; i += 32) {
                        unsigned int uv = LUTs[p0 + i];
                        int u = uv & 255, v = uv >> 8;
                        if (h == 0) {
                            #pragma unroll
                            for (int e = 0; e < 4; ++e)
                                PG[e*CH + i] = feat[e*128 + u] * feat[e*128 + v];
                        } else {
                            #pragma unroll
                            for (int e = 0; e < 4; ++e) {
                                const float* fu = feat + e*128 + 32 + u*3;
                                const float* fv = feat + e*128 + 32 + v*3;
                                PG[e*CH + i] = fmaf(fu[0], fv[0],
                                                fmaf(fu[1], fv[1], fu[2]*fv[2]));
                            }
                        }
                    }
                    __syncwarp();
                    // ---- contract chunk ----
                    const int pb0 = (h * 528 + p0) >> 2;
                    const float4* W4  = (const float4*)Wsm;
                    const float4* P0  = (const float4*)(PG);
                    const float4* P1  = (const float4*)(PG + CH);
                    const float4* P2  = (const float4*)(PG + 2*CH);
                    const float4* P3  = (const float4*)(PG + 3*CH);
                    #pragma unroll 2
                    for (int b = 0; b < CH/4; ++b) {
                        float4 wv = W4[(pb0 + b)*32 + lane];
                        float4 f0 = P0[b], f1 = P1[b], f2 = P2[b], f3 = P3[b];
                        a0_0 = fmaf(wv.x, f0.x, a0_0); a1_0 = fmaf(wv.y, f0.y, a1_0);
                        a0_0 = fmaf(wv.z, f0.z, a0_0); a1_0 = fmaf(wv.w, f0.w, a1_0);
                        a0_1 = fmaf(wv.x, f1.x, a0_1); a1_1 = fmaf(wv.y, f1.y, a1_1);
                        a0_1 = fmaf(wv.z, f1.z, a0_1); a1_1 = fmaf(wv.w, f1.w, a1_1);
                        a0_2 = fmaf(wv.x, f2.x, a0_2); a1_2 = fmaf(wv.y, f2.y, a1_2);
                        a0_2 = fmaf(wv.z, f2.z, a0_2); a1_2 = fmaf(wv.w, f2.w, a1_2);
                        a0_3 = fmaf(wv.x, f3.x, a0_3); a1_3 = fmaf(wv.y, f3.y, a1_3);
                        a0_3 = fmaf(wv.z, f3.z, a0_3); a1_3 = fmaf(wv.w, f3.w, a1_3);
                    }
                    __syncwarp();
                }
            }
            float ys[4] = { a0_0 + a1_0, a0_1 + a1_1, a0_2 + a1_2, a0_3 + a1_3 };
            #pragma unroll
            for (int e = 0; e < 4; ++e) {
                if (g*4 + e < count) {
                    float* o = out + (size_t)(e0 + e)*128 + lane;
                    *o = (t == 0) ? ys[e] : (*o + ys[e]);
                }
            }
        }

        // ================= vector phase =================
        __syncthreads();
        {
            const float4* src = (const float4*)(g_WV + t * WV_FLOATS);
            float4* dst = (float4*)Wsm;
            for (int i = tid; i < WV_FLOATS/4; i += 512) dst[i] = src[i];
        }
        __syncthreads();

        for (int g = warp; g * 4 < count; g += NWARPS) {
            const int e0 = base + g * 4;
            #pragma unroll
            for (int e = 0; e < 4; ++e) {
                int ee = e0 + e; if (ee >= EDIM) ee = EDIM - 1;
                ((float4*)(feat + e*128))[lane] =
                    ((const float4*)(g_Xk + ((size_t)ee*4 + t)*128))[lane];
            }
            __syncwarp();
            #pragma unroll
            for (int e = 0; e < 4; ++e) S4[lane*4 + e] = feat[e*128 + lane];
            __syncwarp();

            float y0[4] = {0,0,0,0}, y1[4] = {0,0,0,0}, y2[4] = {0,0,0,0};

            #pragma unroll 1
            for (int vc = 0; vc < 32; vc += 8) {
                float cacc[8][4];
                #pragma unroll
                for (int j = 0; j < 8; ++j)
                    #pragma unroll
                    for (int e = 0; e < 4; ++e) cacc[j][e] = 0.f;

                #pragma unroll 4
                for (int u = 0; u < 32; ++u) {
                    float4 s4v = *((const float4*)(S4 + u*4));                     // uniform
                    float4 wA  = *((const float4*)(Wsm + u*1152 + lane*36 + vc));
                    float4 wB  = *((const float4*)(Wsm + u*1152 + lane*36 + vc + 4));
                    float sA[4] = { s4v.x, s4v.y, s4v.z, s4v.w };
                    float wAa[4] = { wA.x, wA.y, wA.z, wA.w };
                    float wBa[4] = { wB.x, wB.y, wB.z, wB.w };
                    #pragma unroll
                    for (int j = 0; j < 4; ++j)
                        #pragma unroll
                        for (int e = 0; e < 4; ++e) {
                            cacc[j][e]   = fmaf(wAa[j], sA[e], cacc[j][e]);
                            cacc[4+j][e] = fmaf(wBa[j], sA[e], cacc[4+j][e]);
                        }
                }
                #pragma unroll
                for (int j = 0; j < 8; ++j) {
                    const int v = vc + j;
                    #pragma unroll
                    for (int e = 0; e < 4; ++e) {
                        float cv = cacc[j][e];
                        const float* fv = feat + e*128 + 32 + v*3;   // uniform
                        y0[e] = fmaf(cv, fv[0], y0[e]);
                        y1[e] = fmaf(cv, fv[1], y1[e]);
                        y2[e] = fmaf(cv, fv[2], y2[e]);
                    }
                }
            }
            #pragma unroll
            for (int e = 0; e < 4; ++e) {
                if (g*4 + e < count) {
                    float* o = out + (size_t)(e0 + e)*128 + 32 + lane*3;
                    if (t == 0) { o[0] = y0[e];  o[1] = y1[e];  o[2] = y2[e]; }
                    else        { o[0] += y0[e]; o[1] += y1[e]; o[2] += y2[e]; }
                }
            }
        }
    }
}

// ---------------------------------------------------------------------------
extern "C" void kernel_launch(void* const* d_in, const int* in_sizes, int n_in,
                              void* d_out, int out_size) {
    const float* x  = (const float*)d_in[0];
    const float* Ws = (const float*)d_in[1];
    const float* Wf = (const float*)d_in[2];
    const float* Wn = (const float*)d_in[3];
    const float* Wa = (const float*)d_in[4];

    const int smem_floats = WV_FLOATS + NWARPS*4*CH + NWARPS*512 + NWARPS*128 + 264;
    const int smem_bytes  = smem_floats * 4;   // ~212 KB
    cudaFuncSetAttribute(petp_main, cudaFuncAttributeMaxDynamicSharedMemorySize, smem_bytes);

    prep<<<17408, 128>>>(x, Ws, Wf, Wn, Wa);
    petp_main<<<NCTA, 512, smem_bytes>>>((float*)d_out);
}

// round 9
// speedup vs baseline: 1.0019x; 1.0019x over previous
#include <cuda_runtime.h>

// ---------------------------------------------------------------------------
// PETP_Quadratic v2: 4-element-per-warp register/LDS.128 blocked CTP.
//   y_s[w]   = sum_p WS[p,w] * PG[p]       (PG = 528 s-pairs + 528 gram pairs)
//   y_v[w,k] = sum_v (sum_u s_u WV[u,v,w]) v[v,k]
// ---------------------------------------------------------------------------

#define EDIM  98304
#define NPAIR 528
#define WS_FLOATS (1056*32)       // 33792, layout [p/4][w][4]
#define WV_FLOATS (32*32*36)      // 36864, layout [u][w][v pad 36]
#define NCTA   148
#define EPC    665                // 148*665 = 98420 >= 98304
#define NWARPS 16
#define CH     88                 // pairs per build chunk, 528 = 6*88
#define NCHUNK 6

__device__ float g_WS[4 * WS_FLOATS];
__device__ float g_WV[4 * WV_FLOATS];
__device__ unsigned short g_LUT[NPAIR];
__device__ float g_Xk[(size_t)EDIM * 4 * 128];

// ---------------------------------------------------------------------------
// Prep: blocks [0,1024) do weights, blocks [1024, 17408) do features.
// ---------------------------------------------------------------------------
__global__ void prep(const float* __restrict__ x,
                     const float* __restrict__ Ws, const float* __restrict__ Wf,
                     const float* __restrict__ Wn, const float* __restrict__ Wa) {
    int blk = blockIdx.x;
    if (blk < 1024) {
        int tid = blk * 128 + threadIdx.x;        // 0..131071
        int w = tid & 31;
        int v = (tid >> 5) & 31;
        int u = (tid >> 10) & 31;
        int t = tid >> 15;
        const float* Wt = (t == 0) ? Ws : (t == 1) ? Wf : (t == 2) ? Wn : Wa;
        const float norm = 0.022097086912079608f;   // 1/(32*sqrt(2))
        const float i3   = 0.5773502691896258f;     // 1/sqrt(3)

        float w2 = Wt[2*32768 + (u*32 + v)*32 + w];
        float w3 = Wt[3*32768 + (v*32 + u)*32 + w];
        g_WV[t*WV_FLOATS + u*1152 + w*36 + v] = norm * (w2 + w3);

        if (u <= v) {
            int p = ((u * (65 - u)) >> 1) + (v - u);
            float a0 = Wt[0*32768 + (u*32 + v)*32 + w];
            float a1 = Wt[1*32768 + (u*32 + v)*32 + w];
            if (u != v) {
                a0 += Wt[0*32768 + (v*32 + u)*32 + w];
                a1 += Wt[1*32768 + (v*32 + u)*32 + w];
            }
            int q  = p;
            int q2 = 528 + p;
            g_WS[t*WS_FLOATS + (q  >> 2)*128 + w*4 + (q  & 3)] = norm * a0;
            g_WS[t*WS_FLOATS + (q2 >> 2)*128 + w*4 + (q2 & 3)] = norm * i3 * a1;
            if (t == 0 && w == 0) g_LUT[p] = (unsigned short)(u | (v << 8));
        }
    } else {
        int b  = blk - 1024;     // 0..16383
        int ch = threadIdx.x;    // 0..127
        const float* xb = x + (size_t)b * 6 * 128 + ch;
        float xv[6];
        #pragma unroll
        for (int q = 0; q < 6; q++) xv[q] = xb[q * 128];
        float r0 = xv[0] + xv[1] + xv[2];
        float r1 = xv[3] + xv[4] + xv[5];
        float c0 = xv[0] + xv[3];
        float c1 = xv[1] + xv[4];
        float c2 = xv[2] + xv[5];
        float tot = r0 + r1;
        float* o = g_Xk + (size_t)b * 6 * 4 * 128 + ch;
        #pragma unroll
        for (int i = 0; i < 2; i++) {
            float ri = i ? r1 : r0;
            #pragma unroll
            for (int j = 0; j < 3; j++) {
                float cj = (j == 0) ? c0 : (j == 1) ? c1 : c2;
                float xs = xv[i*3 + j];
                float xf = (ri - xs) * 0.5f;
                float xn = (cj - xs);
                float xa = (tot - ri - cj + xs) * 0.5f;
                float* oe = o + (size_t)(i*3 + j) * 512;
                oe[0]   = xs;
                oe[128] = xf;
                oe[256] = xn;
                oe[384] = xa;
            }
        }
    }
}

// ---------------------------------------------------------------------------
// Main: 148 CTAs x 512 threads. Warp processes 4 elements at a time.
// ---------------------------------------------------------------------------
__global__ void __launch_bounds__(512, 1) petp_main(float* __restrict__ out) {
    extern __shared__ float sm[];
    float* Wsm     = sm;                                   // 36864 floats max
    float* PGall   = sm + WV_FLOATS;                       // 16 * 4 * 88
    float* featall = PGall + NWARPS * 4 * CH;              // 16 * 512
    float* S4all   = featall + NWARPS * 512;               // 16 * 128
    unsigned short* LUTs = (unsigned short*)(S4all + NWARPS * 128);  // 528 u16

    const int tid  = threadIdx.x;
    const int warp = tid >> 5;
    const int lane = tid & 31;
    float* PG   = PGall   + warp * 4 * CH;
    float* feat = featall + warp * 512;
    float* S4   = S4all   + warp * 128;

    for (int i = tid; i < NPAIR; i += 512) LUTs[i] = g_LUT[i];

    const int base  = blockIdx.x * EPC;
    const int count = (EPC < EDIM - base) ? EPC : (EDIM - base);

    for (int t = 0; t < 4; ++t) {
        // ================= scalar phase =================
        __syncthreads();
        {
            const float4* src = (const float4*)(g_WS + t * WS_FLOATS);
            float4* dst = (float4*)Wsm;
            for (int i = tid; i < WS_FLOATS/4; i += 512) dst[i] = src[i];
        }
        __syncthreads();

        for (int g = warp; g * 4 < count; g += NWARPS) {
            const int e0 = base + g * 4;
            #pragma unroll
            for (int e = 0; e < 4; ++e) {
                int ee = e0 + e; if (ee >= EDIM) ee = EDIM - 1;
                ((float4*)(feat + e*128))[lane] =
                    ((const float4*)(g_Xk + ((size_t)ee*4 + t)*128))[lane];
            }
            __syncwarp();

            float a0_0=0.f,a0_1=0.f,a0_2=0.f,a0_3=0.f;
            float a1_0=0.f,a1_1=0.f,a1_2=0.f,a1_3=0.f;

            #pragma unroll 1
            for (int h = 0; h < 2; ++h) {
                #pragma unroll 1
                for (int c = 0; c < NCHUNK; ++c) {
                    const int p0 = c * CH;
                    // ---- build chunk ----
                    for (int i = lane; i < CH; i += 32) {
                        unsigned int uv = LUTs[p0 + i];
                        int u = uv & 255, v = uv >> 8;
                        if (h == 0) {
                            #pragma unroll
                            for (int e = 0; e < 4; ++e)
                                PG[e*CH + i] = feat[e*128 + u] * feat[e*128 + v];
                        } else {
                            #pragma unroll
                            for (int e = 0; e < 4; ++e) {
                                const float* fu = feat + e*128 + 32 + u*3;
                                const float* fv = feat + e*128 + 32 + v*3;
                                PG[e*CH + i] = fmaf(fu[0], fv[0],
                                                fmaf(fu[1], fv[1], fu[2]*fv[2]));
                            }
                        }
                    }
                    __syncwarp();
                    // ---- contract chunk ----
                    const int pb0 = (h * 528 + p0) >> 2;
                    const float4* W4  = (const float4*)Wsm;
                    const float4* P0  = (const float4*)(PG);
                    const float4* P1  = (const float4*)(PG + CH);
                    const float4* P2  = (const float4*)(PG + 2*CH);
                    const float4* P3  = (const float4*)(PG + 3*CH);
                    #pragma unroll 2
                    for (int b = 0; b < CH/4; ++b) {
                        float4 wv = W4[(pb0 + b)*32 + lane];
                        float4 f0 = P0[b], f1 = P1[b], f2 = P2[b], f3 = P3[b];
                        a0_0 = fmaf(wv.x, f0.x, a0_0); a1_0 = fmaf(wv.y, f0.y, a1_0);
                        a0_0 = fmaf(wv.z, f0.z, a0_0); a1_0 = fmaf(wv.w, f0.w, a1_0);
                        a0_1 = fmaf(wv.x, f1.x, a0_1); a1_1 = fmaf(wv.y, f1.y, a1_1);
                        a0_1 = fmaf(wv.z, f1.z, a0_1); a1_1 = fmaf(wv.w, f1.w, a1_1);
                        a0_2 = fmaf(wv.x, f2.x, a0_2); a1_2 = fmaf(wv.y, f2.y, a1_2);
                        a0_2 = fmaf(wv.z, f2.z, a0_2); a1_2 = fmaf(wv.w, f2.w, a1_2);
                        a0_3 = fmaf(wv.x, f3.x, a0_3); a1_3 = fmaf(wv.y, f3.y, a1_3);
                        a0_3 = fmaf(wv.z, f3.z, a0_3); a1_3 = fmaf(wv.w, f3.w, a1_3);
                    }
                    __syncwarp();
                }
            }
            float ys[4] = { a0_0 + a1_0, a0_1 + a1_1, a0_2 + a1_2, a0_3 + a1_3 };
            #pragma unroll
            for (int e = 0; e < 4; ++e) {
                if (g*4 + e < count) {
                    float* o = out + (size_t)(e0 + e)*128 + lane;
                    *o = (t == 0) ? ys[e] : (*o + ys[e]);
                }
            }
        }

        // ================= vector phase =================
        __syncthreads();
        {
            const float4* src = (const float4*)(g_WV + t * WV_FLOATS);
            float4* dst = (float4*)Wsm;
            for (int i = tid; i < WV_FLOATS/4; i += 512) dst[i] = src[i];
        }
        __syncthreads();

        for (int g = warp; g * 4 < count; g += NWARPS) {
            const int e0 = base + g * 4;
            #pragma unroll
            for (int e = 0; e < 4; ++e) {
                int ee = e0 + e; if (ee >= EDIM) ee = EDIM - 1;
                ((float4*)(feat + e*128))[lane] =
                    ((const float4*)(g_Xk + ((size_t)ee*4 + t)*128))[lane];
            }
            __syncwarp();
            #pragma unroll
            for (int e = 0; e < 4; ++e) S4[lane*4 + e] = feat[e*128 + lane];
            __syncwarp();

            float y0[4] = {0,0,0,0}, y1[4] = {0,0,0,0}, y2[4] = {0,0,0,0};

            #pragma unroll 1
            for (int vc = 0; vc < 32; vc += 8) {
                float cacc[8][4];
                #pragma unroll
                for (int j = 0; j < 8; ++j)
                    #pragma unroll
                    for (int e = 0; e < 4; ++e) cacc[j][e] = 0.f;

                #pragma unroll 4
                for (int u = 0; u < 32; ++u) {
                    float4 s4v = *((const float4*)(S4 + u*4));                     // uniform
                    float4 wA  = *((const float4*)(Wsm + u*1152 + lane*36 + vc));
                    float4 wB  = *((const float4*)(Wsm + u*1152 + lane*36 + vc + 4));
                    float sA[4] = { s4v.x, s4v.y, s4v.z, s4v.w };
                    float wAa[4] = { wA.x, wA.y, wA.z, wA.w };
                    float wBa[4] = { wB.x, wB.y, wB.z, wB.w };
                    #pragma unroll
                    for (int j = 0; j < 4; ++j)
                        #pragma unroll
                        for (int e = 0; e < 4; ++e) {
                            cacc[j][e]   = fmaf(wAa[j], sA[e], cacc[j][e]);
                            cacc[4+j][e] = fmaf(wBa[j], sA[e], cacc[4+j][e]);
                        }
                }
                #pragma unroll
                for (int j = 0; j < 8; ++j) {
                    const int v = vc + j;
                    #pragma unroll
                    for (int e = 0; e < 4; ++e) {
                        float cv = cacc[j][e];
                        const float* fv = feat + e*128 + 32 + v*3;   // uniform
                        y0[e] = fmaf(cv, fv[0], y0[e]);
                        y1[e] = fmaf(cv, fv[1], y1[e]);
                        y2[e] = fmaf(cv, fv[2], y2[e]);
                    }
                }
            }
            #pragma unroll
            for (int e = 0; e < 4; ++e) {
                if (g*4 + e < count) {
                    float* o = out + (size_t)(e0 + e)*128 + 32 + lane*3;
                    if (t == 0) { o[0] = y0[e];  o[1] = y1[e];  o[2] = y2[e]; }
                    else        { o[0] += y0[e]; o[1] += y1[e]; o[2] += y2[e]; }
                }
            }
        }
    }
}

// ---------------------------------------------------------------------------
extern "C" void kernel_launch(void* const* d_in, const int* in_sizes, int n_in,
                              void* d_out, int out_size) {
    const float* x  = (const float*)d_in[0];
    const float* Ws = (const float*)d_in[1];
    const float* Wf = (const float*)d_in[2];
    const float* Wn = (const float*)d_in[3];
    const float* Wa = (const float*)d_in[4];

    const int smem_floats = WV_FLOATS + NWARPS*4*CH + NWARPS*512 + NWARPS*128 + 264;
    const int smem_bytes  = smem_floats * 4;   // ~212 KB
    cudaFuncSetAttribute(petp_main, cudaFuncAttributeMaxDynamicSharedMemorySize, smem_bytes);

    prep<<<17408, 128>>>(x, Ws, Wf, Wn, Wa);
    petp_main<<<NCTA, 512, smem_bytes>>>((float*)d_out);
}

// round 11
// speedup vs baseline: 1.4438x; 1.4411x over previous
#include <cuda_runtime.h>
#include <cstdint>

#define EDIM 98304

// Weights in exact mma A-fragment order: [kind][mat][a][ks][mf][lane][4] (tf32 bits)
__device__ uint32_t g_Wfrag[4 * 3 * 32768];
// Features: [kind][e][ s(0..31) | vx(32..63) | vy(64..95) | vz(96..127) ]
__device__ float g_F[(size_t)4 * EDIM * 128];

#define MMA(c, A, b0, b1) \
    asm volatile("mma.sync.aligned.m16n8k8.row.col.f32.tf32.tf32.f32 " \
        "{%0,%1,%2,%3},{%4,%5,%6,%7},{%8,%9},{%0,%1,%2,%3};" \
        : "+f"((c)[0]), "+f"((c)[1]), "+f"((c)[2]), "+f"((c)[3]) \
        : "r"((A).x), "r"((A).y), "r"((A).z), "r"((A).w), "r"(b0), "r"(b1))

__device__ __forceinline__ uint32_t cvt_tf32(float p) {
    uint32_t u;
    asm("cvt.rn.tf32.f32 %0, %1;" : "=r"(u) : "f"(p));
    return u;
}

// ---------------------------------------------------------------------------
// prep_w: one thread per tf32 weight value, written in fragment order.
//   mat 0: norm*W0 ; mat 1: norm/sqrt3*W1 ; mat 2: norm*(W2[a,j]+W3[j,a])
//   A-frag (m16n8k8 row): c0:(w=g,j=8ks+tig) c1:(w=g+8) c2:(j+4) c3:(w+8,j+4)
// ---------------------------------------------------------------------------
__global__ void prep_w(const float* __restrict__ Ws, const float* __restrict__ Wf,
                       const float* __restrict__ Wn, const float* __restrict__ Wa) {
    int i = blockIdx.x * 256 + threadIdx.x;    // 0..393215
    int c    = i & 3;
    int lane = (i >> 2) & 31;
    int mf   = (i >> 7) & 1;
    int ks   = (i >> 8) & 3;
    int a    = (i >> 10) & 31;
    int mk   = i >> 15;                        // 0..11
    int mat = mk % 3, kind = mk / 3;
    const float* W = (kind == 0) ? Ws : (kind == 1) ? Wf : (kind == 2) ? Wn : Wa;
    const float norm = 0.022097086912079608f;  // 1/(32*sqrt(2))
    const float i3   = 0.5773502691896258f;    // 1/sqrt(3)
    int g = lane >> 2, tig = lane & 3;
    int w = g + 8 * (c & 1) + 16 * mf;
    int j = 8 * ks + tig + 4 * (c >> 1);
    float val;
    if      (mat == 0) val = norm * W[(a * 32 + j) * 32 + w];
    else if (mat == 1) val = norm * i3 * W[32768 + (a * 32 + j) * 32 + w];
    else               val = norm * (W[65536 + (a * 32 + j) * 32 + w] +
                                     W[98304 + (j * 32 + a) * 32 + w]);
    g_Wfrag[i] = cvt_tf32(val);
}

// ---------------------------------------------------------------------------
// prep_f: permutation-equivariant features, k-major vector planes.
// ---------------------------------------------------------------------------
__global__ void prep_f(const float* __restrict__ x) {
    int b = blockIdx.x, ch = threadIdx.x;
    const float* xb = x + (size_t)b * 6 * 128 + ch;
    float xv[6];
    #pragma unroll
    for (int q = 0; q < 6; q++) xv[q] = xb[q * 128];
    float r0 = xv[0]+xv[1]+xv[2], r1 = xv[3]+xv[4]+xv[5];
    float c0 = xv[0]+xv[3], c1 = xv[1]+xv[4], c2 = xv[2]+xv[5];
    float tot = r0 + r1;
    int pos = (ch < 32) ? ch : 32 + ((ch - 32) % 3) * 32 + (ch - 32) / 3;
    #pragma unroll
    for (int i = 0; i < 2; i++) {
        float ri = i ? r1 : r0;
        #pragma unroll
        for (int jj = 0; jj < 3; jj++) {
            float cj = (jj == 0) ? c0 : (jj == 1) ? c1 : c2;
            float xs = xv[i * 3 + jj];
            float vals[4] = { xs, (ri - xs) * 0.5f, (cj - xs),
                              (tot - ri - cj + xs) * 0.5f };
            size_t e = (size_t)b * 6 + i * 3 + jj;
            #pragma unroll
            for (int t = 0; t < 4; t++)
                g_F[((size_t)t * EDIM + e) * 128 + pos] = vals[t];
        }
    }
}

// ---------------------------------------------------------------------------
// Main: 768 CTAs x 128 threads (4 warps). Warp tile: 32 w x 32 elements.
//   A-operand = weights (LDG.128 fragment loads, L1-resident)
//   B-operand = per-element products built in registers, cvt.rn to tf32
//   blk 0: y_s (scalar sec + gram sec); blk 1..3: y_v k-components.
// ---------------------------------------------------------------------------
__global__ void __launch_bounds__(128) petp_mma(float* __restrict__ out) {
    extern __shared__ float FS[];                   // 128 rows x 132 (padded)
    const int tid = threadIdx.x, warp = tid >> 5, lane = tid & 31;
    const int g = lane >> 2, tig = lane & 3;
    const int e0 = blockIdx.x * 128 + warp * 32;

    for (int blk = 0; blk < 4; ++blk) {
        float acc[2][4][4];
        #pragma unroll
        for (int mf = 0; mf < 2; ++mf)
            #pragma unroll
            for (int nf = 0; nf < 4; ++nf)
                #pragma unroll
                for (int q = 0; q < 4; ++q) acc[mf][nf][q] = 0.f;

        for (int kind = 0; kind < 4; ++kind) {
            __syncthreads();
            {   // stage this kind's 128-element feature tile
                const float4* src = (const float4*)(g_F +
                    ((size_t)kind * EDIM + blockIdx.x * 128 + tid) * 128);
                float4* dst = (float4*)(FS + tid * 132);
                #pragma unroll 8
                for (int q = 0; q < 32; ++q) dst[q] = src[q];
            }
            __syncthreads();
            const float* fr0 = FS + (warp * 32 + g) * 132;   // + nf*8*132 per n-frag

            if (blk == 0) {
                // ---------- scalar section: b = s_a * s_j, B = W0 ----------
                float bs[4][8];
                #pragma unroll
                for (int nf = 0; nf < 4; ++nf)
                    #pragma unroll
                    for (int jj = 0; jj < 8; ++jj)
                        bs[nf][jj] = fr0[nf * 1056 + tig + 4 * jj];
                {
                    const uint4* wp = (const uint4*)g_Wfrag + (kind * 3 + 0) * 8192;
                    #pragma unroll 1
                    for (int a = 0; a < 32; ++a) {
                        float al[4];
                        #pragma unroll
                        for (int nf = 0; nf < 4; ++nf) al[nf] = fr0[nf * 1056 + a];
                        #pragma unroll
                        for (int ks = 0; ks < 4; ++ks) {
                            uint4 A0 = wp[a * 256 + ks * 64 + lane];
                            uint4 A1 = wp[a * 256 + ks * 64 + 32 + lane];
                            uint32_t b0[4], b1[4];
                            #pragma unroll
                            for (int nf = 0; nf < 4; ++nf) {
                                b0[nf] = cvt_tf32(al[nf] * bs[nf][2 * ks]);
                                b1[nf] = cvt_tf32(al[nf] * bs[nf][2 * ks + 1]);
                            }
                            #pragma unroll
                            for (int nf = 0; nf < 4; ++nf) {
                                MMA(acc[0][nf], A0, b0[nf], b1[nf]);
                                MMA(acc[1][nf], A1, b0[nf], b1[nf]);
                            }
                        }
                    }
                }
                // ---------- gram section: b = v_a . v_j, B = i3*W1 ----------
                float bv[3][4][8];
                #pragma unroll
                for (int k = 0; k < 3; ++k)
                    #pragma unroll
                    for (int nf = 0; nf < 4; ++nf)
                        #pragma unroll
                        for (int jj = 0; jj < 8; ++jj)
                            bv[k][nf][jj] = fr0[nf * 1056 + 32 + 32 * k + tig + 4 * jj];
                {
                    const uint4* wp = (const uint4*)g_Wfrag + (kind * 3 + 1) * 8192;
                    #pragma unroll 1
                    for (int a = 0; a < 32; ++a) {
                        float a3[4][3];
                        #pragma unroll
                        for (int nf = 0; nf < 4; ++nf)
                            #pragma unroll
                            for (int k = 0; k < 3; ++k)
                                a3[nf][k] = fr0[nf * 1056 + 32 + 32 * k + a];
                        #pragma unroll
                        for (int ks = 0; ks < 4; ++ks) {
                            uint4 A0 = wp[a * 256 + ks * 64 + lane];
                            uint4 A1 = wp[a * 256 + ks * 64 + 32 + lane];
                            uint32_t b0[4], b1[4];
                            #pragma unroll
                            for (int nf = 0; nf < 4; ++nf) {
                                float p0 = fmaf(a3[nf][0], bv[0][nf][2*ks],
                                           fmaf(a3[nf][1], bv[1][nf][2*ks],
                                                a3[nf][2] * bv[2][nf][2*ks]));
                                float p1 = fmaf(a3[nf][0], bv[0][nf][2*ks+1],
                                           fmaf(a3[nf][1], bv[1][nf][2*ks+1],
                                                a3[nf][2] * bv[2][nf][2*ks+1]));
                                b0[nf] = cvt_tf32(p0);
                                b1[nf] = cvt_tf32(p1);
                            }
                            #pragma unroll
                            for (int nf = 0; nf < 4; ++nf) {
                                MMA(acc[0][nf], A0, b0[nf], b1[nf]);
                                MMA(acc[1][nf], A1, b0[nf], b1[nf]);
                            }
                        }
                    }
                }
            } else {
                // ---------- vector section: b = s_a * v_jk, B = W2+W3^T ----------
                float bb[4][8];
                #pragma unroll
                for (int nf = 0; nf < 4; ++nf)
                    #pragma unroll
                    for (int jj = 0; jj < 8; ++jj)
                        bb[nf][jj] = fr0[nf * 1056 + 32 * blk + tig + 4 * jj];
                const uint4* wp = (const uint4*)g_Wfrag + (kind * 3 + 2) * 8192;
                #pragma unroll 1
                for (int a = 0; a < 32; ++a) {
                    float al[4];
                    #pragma unroll
                    for (int nf = 0; nf < 4; ++nf) al[nf] = fr0[nf * 1056 + a];
                    #pragma unroll
                    for (int ks = 0; ks < 4; ++ks) {
                        uint4 A0 = wp[a * 256 + ks * 64 + lane];
                        uint4 A1 = wp[a * 256 + ks * 64 + 32 + lane];
                        uint32_t b0[4], b1[4];
                        #pragma unroll
                        for (int nf = 0; nf < 4; ++nf) {
                            b0[nf] = cvt_tf32(al[nf] * bb[nf][2 * ks]);
                            b1[nf] = cvt_tf32(al[nf] * bb[nf][2 * ks + 1]);
                        }
                        #pragma unroll
                        for (int nf = 0; nf < 4; ++nf) {
                            MMA(acc[0][nf], A0, b0[nf], b1[nf]);
                            MMA(acc[1][nf], A1, b0[nf], b1[nf]);
                        }
                    }
                }
            }
        }

        // ---------------- epilogue for this output block ----------------
        #pragma unroll
        for (int mf = 0; mf < 2; ++mf)
            #pragma unroll
            for (int nf = 0; nf < 4; ++nf) {
                int e  = e0 + 8 * nf + 2 * tig;
                int w1 = g + 16 * mf, w2 = w1 + 8;
                int of1 = (blk == 0) ? w1 : (31 + blk + 3 * w1);
                int of2 = (blk == 0) ? w2 : (31 + blk + 3 * w2);
                float* o = out + (size_t)e * 128;
                o[of1]       = acc[mf][nf][0];
                o[128 + of1] = acc[mf][nf][1];
                o[of2]       = acc[mf][nf][2];
                o[128 + of2] = acc[mf][nf][3];
            }
    }
}

// ---------------------------------------------------------------------------
extern "C" void kernel_launch(void* const* d_in, const int* in_sizes, int n_in,
                              void* d_out, int out_size) {
    const float* x  = (const float*)d_in[0];
    const float* Ws = (const float*)d_in[1];
    const float* Wf = (const float*)d_in[2];
    const float* Wn = (const float*)d_in[3];
    const float* Wa = (const float*)d_in[4];

    const int smem = 128 * 132 * 4;   // 67584 B
    cudaFuncSetAttribute(petp_mma, cudaFuncAttributeMaxDynamicSharedMemorySize, smem);

    prep_w<<<1536, 256>>>(Ws, Wf, Wn, Wa);
    prep_f<<<16384, 128>>>(x);
    petp_mma<<<768, 128, smem>>>((float*)d_out);
}

// round 12
// speedup vs baseline: 1.9194x; 1.3294x over previous
#include <cuda_runtime.h>
#include <cstdint>

#define EDIM 98304
#define PAD  133
#define NFS  (8 * PAD)   // 1064, nf row stride

// Weights in exact mma A-fragment order: [kind][mat][a][ks][mf][lane][4] (tf32 bits)
__device__ uint32_t g_Wfrag[4 * 3 * 32768];
// Features: [kind][e][ s(0..31) | vx(32..63) | vy(64..95) | vz(96..127) ]
__device__ float g_F[(size_t)4 * EDIM * 128];

#define MMA(c, A, b0, b1) \
    asm volatile("mma.sync.aligned.m16n8k8.row.col.f32.tf32.tf32.f32 " \
        "{%0,%1,%2,%3},{%4,%5,%6,%7},{%8,%9},{%0,%1,%2,%3};" \
        : "+f"((c)[0]), "+f"((c)[1]), "+f"((c)[2]), "+f"((c)[3]) \
        : "r"((A).x), "r"((A).y), "r"((A).z), "r"((A).w), "r"(b0), "r"(b1))

__device__ __forceinline__ uint32_t cvt_tf32(float p) {
    uint32_t u;
    asm("cvt.rn.tf32.f32 %0, %1;" : "=r"(u) : "f"(p));
    return u;
}

// ---------------------------------------------------------------------------
// prep_w: one thread per tf32 weight value, in fragment order (same as R11).
// ---------------------------------------------------------------------------
__global__ void prep_w(const float* __restrict__ Ws, const float* __restrict__ Wf,
                       const float* __restrict__ Wn, const float* __restrict__ Wa) {
    int i = blockIdx.x * 256 + threadIdx.x;
    int c    = i & 3;
    int lane = (i >> 2) & 31;
    int mf   = (i >> 7) & 1;
    int ks   = (i >> 8) & 3;
    int a    = (i >> 10) & 31;
    int mk   = i >> 15;
    int mat = mk % 3, kind = mk / 3;
    const float* W = (kind == 0) ? Ws : (kind == 1) ? Wf : (kind == 2) ? Wn : Wa;
    const float norm = 0.022097086912079608f;
    const float i3   = 0.5773502691896258f;
    int g = lane >> 2, tig = lane & 3;
    int w = g + 8 * (c & 1) + 16 * mf;
    int j = 8 * ks + tig + 4 * (c >> 1);
    float val;
    if      (mat == 0) val = norm * W[(a * 32 + j) * 32 + w];
    else if (mat == 1) val = norm * i3 * W[32768 + (a * 32 + j) * 32 + w];
    else               val = norm * (W[65536 + (a * 32 + j) * 32 + w] +
                                     W[98304 + (j * 32 + a) * 32 + w]);
    g_Wfrag[i] = cvt_tf32(val);
}

// ---------------------------------------------------------------------------
// prep_f: permutation-equivariant features, k-major vector planes (same R11).
// ---------------------------------------------------------------------------
__global__ void prep_f(const float* __restrict__ x) {
    int b = blockIdx.x, ch = threadIdx.x;
    const float* xb = x + (size_t)b * 6 * 128 + ch;
    float xv[6];
    #pragma unroll
    for (int q = 0; q < 6; q++) xv[q] = xb[q * 128];
    float r0 = xv[0]+xv[1]+xv[2], r1 = xv[3]+xv[4]+xv[5];
    float c0 = xv[0]+xv[3], c1 = xv[1]+xv[4], c2 = xv[2]+xv[5];
    float tot = r0 + r1;
    int pos = (ch < 32) ? ch : 32 + ((ch - 32) % 3) * 32 + (ch - 32) / 3;
    #pragma unroll
    for (int i = 0; i < 2; i++) {
        float ri = i ? r1 : r0;
        #pragma unroll
        for (int jj = 0; jj < 3; jj++) {
            float cj = (jj == 0) ? c0 : (jj == 1) ? c1 : c2;
            float xs = xv[i * 3 + jj];
            float vals[4] = { xs, (ri - xs) * 0.5f, (cj - xs),
                              (tot - ri - cj + xs) * 0.5f };
            size_t e = (size_t)b * 6 + i * 3 + jj;
            #pragma unroll
            for (int t = 0; t < 4; t++)
                g_F[((size_t)t * EDIM + e) * 128 + pos] = vals[t];
        }
    }
}

// ---------------------------------------------------------------------------
// staging helper: conflict-free STS (pad 133)
// ---------------------------------------------------------------------------
__device__ __forceinline__ void stage_tile(float* FS, int kind, int tileBase, int tid) {
    const float* src = g_F + ((size_t)kind * EDIM + tileBase + tid) * 128;
    float* dst = FS + tid * PAD;
    #pragma unroll 8
    for (int q = 0; q < 32; ++q) {
        float4 v = ((const float4*)src)[q];
        dst[q*4+0] = v.x; dst[q*4+1] = v.y; dst[q*4+2] = v.z; dst[q*4+3] = v.w;
    }
}

// ---------------------------------------------------------------------------
// Main: 768 CTAs x 128 threads. Two passes: y_s (scalar+gram), y_v (3 comps).
// ---------------------------------------------------------------------------
__global__ void __launch_bounds__(128, 2) petp_mma(float* __restrict__ out) {
    extern __shared__ float FS[];   // 128 x 133
    const int tid = threadIdx.x, warp = tid >> 5, lane = tid & 31;
    const int g = lane >> 2, tig = lane & 3;
    const int tileBase = blockIdx.x * 128;
    const int e0 = tileBase + warp * 32;
    const float* fr0 = FS + (warp * 32 + g) * PAD;

    // ================= pass 0: y_s = scalar + gram sections =================
    {
        float acc[2][4][4];
        #pragma unroll
        for (int mf = 0; mf < 2; ++mf)
            #pragma unroll
            for (int nf = 0; nf < 4; ++nf)
                #pragma unroll
                for (int q = 0; q < 4; ++q) acc[mf][nf][q] = 0.f;

        for (int kind = 0; kind < 4; ++kind) {
            __syncthreads();
            stage_tile(FS, kind, tileBase, tid);
            __syncthreads();

            float bs[4][8];
            #pragma unroll
            for (int nf = 0; nf < 4; ++nf)
                #pragma unroll
                for (int jj = 0; jj < 8; ++jj)
                    bs[nf][jj] = fr0[nf * NFS + tig + 4 * jj];

            const uint4* wp0 = (const uint4*)g_Wfrag + (kind * 3 + 0) * 8192;
            const uint4* wp1 = (const uint4*)g_Wfrag + (kind * 3 + 1) * 8192;

            #pragma unroll 1
            for (int a = 0; a < 32; ++a) {
                uint4 S0[4], S1[4], G0[4], G1[4];
                #pragma unroll
                for (int ks = 0; ks < 4; ++ks) {
                    S0[ks] = wp0[a * 256 + ks * 64 + lane];
                    S1[ks] = wp0[a * 256 + ks * 64 + 32 + lane];
                    G0[ks] = wp1[a * 256 + ks * 64 + lane];
                    G1[ks] = wp1[a * 256 + ks * 64 + 32 + lane];
                }
                float al[4], av[4][3];
                #pragma unroll
                for (int nf = 0; nf < 4; ++nf) {
                    al[nf] = fr0[nf * NFS + a];
                    #pragma unroll
                    for (int k = 0; k < 3; ++k)
                        av[nf][k] = fr0[nf * NFS + 32 + 32 * k + a];
                }
                #pragma unroll
                for (int ks = 0; ks < 4; ++ks) {
                    #pragma unroll
                    for (int nf = 0; nf < 4; ++nf) {
                        uint32_t b0 = cvt_tf32(al[nf] * bs[nf][2 * ks]);
                        uint32_t b1 = cvt_tf32(al[nf] * bs[nf][2 * ks + 1]);
                        MMA(acc[0][nf], S0[ks], b0, b1);
                        MMA(acc[1][nf], S1[ks], b0, b1);
                        int cj = tig + 8 * ks;
                        float p0 = fmaf(av[nf][0], fr0[nf*NFS + 32 + cj],
                                   fmaf(av[nf][1], fr0[nf*NFS + 64 + cj],
                                        av[nf][2] * fr0[nf*NFS + 96 + cj]));
                        float p1 = fmaf(av[nf][0], fr0[nf*NFS + 36 + cj],
                                   fmaf(av[nf][1], fr0[nf*NFS + 68 + cj],
                                        av[nf][2] * fr0[nf*NFS + 100 + cj]));
                        uint32_t q0 = cvt_tf32(p0), q1 = cvt_tf32(p1);
                        MMA(acc[0][nf], G0[ks], q0, q1);
                        MMA(acc[1][nf], G1[ks], q0, q1);
                    }
                }
            }
        }
        #pragma unroll
        for (int mf = 0; mf < 2; ++mf)
            #pragma unroll
            for (int nf = 0; nf < 4; ++nf) {
                int e  = e0 + 8 * nf + 2 * tig;
                int w1 = g + 16 * mf, w2 = w1 + 8;
                float* o = out + (size_t)e * 128;
                o[w1]       = acc[mf][nf][0];
                o[128 + w1] = acc[mf][nf][1];
                o[w2]       = acc[mf][nf][2];
                o[128 + w2] = acc[mf][nf][3];
            }
    }

    // ================= pass V: y_v, 3 components share mat2 frags =================
    {
        float acc[3][2][4][4];
        #pragma unroll
        for (int k = 0; k < 3; ++k)
            #pragma unroll
            for (int mf = 0; mf < 2; ++mf)
                #pragma unroll
                for (int nf = 0; nf < 4; ++nf)
                    #pragma unroll
                    for (int q = 0; q < 4; ++q) acc[k][mf][nf][q] = 0.f;

        for (int kind = 0; kind < 4; ++kind) {
            __syncthreads();
            stage_tile(FS, kind, tileBase, tid);
            __syncthreads();

            const uint4* wp2 = (const uint4*)g_Wfrag + (kind * 3 + 2) * 8192;

            #pragma unroll 1
            for (int a = 0; a < 32; ++a) {
                uint4 V0[4], V1[4];
                #pragma unroll
                for (int ks = 0; ks < 4; ++ks) {
                    V0[ks] = wp2[a * 256 + ks * 64 + lane];
                    V1[ks] = wp2[a * 256 + ks * 64 + 32 + lane];
                }
                float al[4];
                #pragma unroll
                for (int nf = 0; nf < 4; ++nf) al[nf] = fr0[nf * NFS + a];

                #pragma unroll
                for (int ks = 0; ks < 4; ++ks) {
                    #pragma unroll
                    for (int nf = 0; nf < 4; ++nf) {
                        int cj = tig + 8 * ks;
                        #pragma unroll
                        for (int k = 0; k < 3; ++k) {
                            uint32_t b0 = cvt_tf32(al[nf] * fr0[nf*NFS + 32 + 32*k + cj]);
                            uint32_t b1 = cvt_tf32(al[nf] * fr0[nf*NFS + 36 + 32*k + cj]);
                            MMA(acc[k][0][nf], V0[ks], b0, b1);
                            MMA(acc[k][1][nf], V1[ks], b0, b1);
                        }
                    }
                }
            }
        }
        #pragma unroll
        for (int k = 0; k < 3; ++k)
            #pragma unroll
            for (int mf = 0; mf < 2; ++mf)
                #pragma unroll
                for (int nf = 0; nf < 4; ++nf) {
                    int e  = e0 + 8 * nf + 2 * tig;
                    int w1 = g + 16 * mf, w2 = w1 + 8;
                    int of1 = 32 + 3 * w1 + k;
                    int of2 = 32 + 3 * w2 + k;
                    float* o = out + (size_t)e * 128;
                    o[of1]       = acc[k][mf][nf][0];
                    o[128 + of1] = acc[k][mf][nf][1];
                    o[of2]       = acc[k][mf][nf][2];
                    o[128 + of2] = acc[k][mf][nf][3];
                }
    }
}

// ---------------------------------------------------------------------------
extern "C" void kernel_launch(void* const* d_in, const int* in_sizes, int n_in,
                              void* d_out, int out_size) {
    const float* x  = (const float*)d_in[0];
    const float* Ws = (const float*)d_in[1];
    const float* Wf = (const float*)d_in[2];
    const float* Wn = (const float*)d_in[3];
    const float* Wa = (const float*)d_in[4];

    const int smem = 128 * PAD * 4;   // 68096 B
    cudaFuncSetAttribute(petp_mma, cudaFuncAttributeMaxDynamicSharedMemorySize, smem);

    prep_w<<<1536, 256>>>(Ws, Wf, Wn, Wa);
    prep_f<<<16384, 128>>>(x);
    petp_mma<<<768, 128, smem>>>((float*)d_out);
}